// round 2
// baseline (speedup 1.0000x reference)
#include <cuda_runtime.h>
#include <cuda_bf16.h>
#include <cstdint>

// SSIM loss map: out = clip((1 - SSIM_3x3(x,y)) * 0.5, 0, 1)
// Input/Output: NCHW fp32, N=16, C=3, H=W=512  -> 48 independent 512x512 planes.
// 3x3 SAME avg pool with count_include_pad=False.

#define IMG_H 512
#define IMG_W 512
#define TILE  32          // 32x32 output tile per block
#define BX    32
#define BY    8
#define RPT   4           // output rows per thread (BY*RPT == TILE)
#define SH_W  34          // tile + 1px halo each side
#define SH_H  34

__global__ __launch_bounds__(BX * BY)
void ssim_kernel(const float* __restrict__ gx,
                 const float* __restrict__ gy,
                 float* __restrict__ gout)
{
    __shared__ float shx[SH_H * SH_W];
    __shared__ float shy[SH_H * SH_W];

    const int tid   = threadIdx.y * BX + threadIdx.x;
    const int plane = blockIdx.z;
    const size_t base = (size_t)plane * (IMG_H * IMG_W);
    const int h0 = blockIdx.y * TILE;   // tile top-left in the image
    const int w0 = blockIdx.x * TILE;

    // ---- cooperative halo-tile load (zero-pad out of bounds) ----
    #pragma unroll
    for (int i = tid; i < SH_H * SH_W; i += BX * BY) {
        int r = i / SH_W;
        int c = i - r * SH_W;
        int gh = h0 - 1 + r;
        int gw = w0 - 1 + c;
        bool ok = ((unsigned)gh < IMG_H) && ((unsigned)gw < IMG_W);
        size_t gi = base + (size_t)gh * IMG_W + gw;
        shx[i] = ok ? gx[gi] : 0.0f;
        shy[i] = ok ? gy[gi] : 0.0f;
    }
    __syncthreads();

    const int lx = threadIdx.x;          // output column within tile (0..31)
    const int gw = w0 + lx;
    // valid-tap count in x direction
    const float cx = 3.0f - (float)(gw == 0) - (float)(gw == IMG_W - 1);

    // Thread covers output local rows r0 .. r0+RPT-1.
    // Needs shared rows r0 .. r0+RPT+1 (shared row s maps to global h0-1+s).
    const int r0 = threadIdx.y * RPT;

    // per-row horizontal 3-tap sums (conflict-free: lanes read consecutive cols)
    float hx[RPT + 2], hy[RPT + 2], hxx[RPT + 2], hyy[RPT + 2], hxy[RPT + 2];
    #pragma unroll
    for (int k = 0; k < RPT + 2; k++) {
        const float* px = &shx[(r0 + k) * SH_W + lx];
        const float* py = &shy[(r0 + k) * SH_W + lx];
        float a0 = px[0], a1 = px[1], a2 = px[2];
        float b0 = py[0], b1 = py[1], b2 = py[2];
        hx [k] = a0 + a1 + a2;
        hy [k] = b0 + b1 + b2;
        hxx[k] = fmaf(a0, a0, fmaf(a1, a1, a2 * a2));
        hyy[k] = fmaf(b0, b0, fmaf(b1, b1, b2 * b2));
        hxy[k] = fmaf(a0, b0, fmaf(a1, b1, a2 * b2));
    }

    const float C1 = 0.01f * 0.01f;
    const float C2 = 0.03f * 0.03f;

    #pragma unroll
    for (int k = 0; k < RPT; k++) {
        const int lr = r0 + k;
        const int gh = h0 + lr;
        const float cy = 3.0f - (float)(gh == 0) - (float)(gh == IMG_H - 1);
        const float inv = 1.0f / (cy * cx);   // matches reference's 1/sum_pool(ones)

        float sx  = hx [k] + hx [k + 1] + hx [k + 2];
        float sy  = hy [k] + hy [k + 1] + hy [k + 2];
        float sxx = hxx[k] + hxx[k + 1] + hxx[k + 2];
        float syy = hyy[k] + hyy[k + 1] + hyy[k + 2];
        float sxy = hxy[k] + hxy[k + 1] + hxy[k + 2];

        float mux = sx * inv;
        float muy = sy * inv;
        float sigx  = fmaf(-mux, mux, sxx * inv);
        float sigy  = fmaf(-muy, muy, syy * inv);
        float sigxy = fmaf(-mux, muy, sxy * inv);

        float num = fmaf(2.0f * mux, muy, C1) * fmaf(2.0f, sigxy, C2);
        float den = fmaf(mux, mux, fmaf(muy, muy, C1)) * (sigx + sigy + C2) + 1e-12f;
        float ssim = __fdividef(num, den);
        float res  = fminf(fmaxf((1.0f - ssim) * 0.5f, 0.0f), 1.0f);

        gout[base + (size_t)gh * IMG_W + gw] = res;
    }
}

extern "C" void kernel_launch(void* const* d_in, const int* in_sizes, int n_in,
                              void* d_out, int out_size)
{
    const float* x = (const float*)d_in[0];
    const float* y = (const float*)d_in[1];
    float* out = (float*)d_out;

    // 48 planes of 512x512; 32x32 tiles
    dim3 block(BX, BY, 1);
    dim3 grid(IMG_W / TILE, IMG_H / TILE, 16 * 3);
    ssim_kernel<<<grid, block>>>(x, y, out);
}

// round 3
// speedup vs baseline: 1.2667x; 1.2667x over previous
#include <cuda_runtime.h>
#include <cuda_bf16.h>
#include <cstdint>

// SSIM loss map: out = clip((1 - SSIM_3x3(x,y)) * 0.5, 0, 1)
// NCHW fp32, 16x3x512x512 = 48 independent 512x512 planes.
// Register-sliding scheme: no shared memory, no barriers.
// Each thread owns a 4-wide float4 column strip and slides over ROWS output
// rows, keeping a 3-row rolling window of horizontal 3-tap sums in registers.

#define IMG   512
#define ROWS  8          // output rows per thread
#define TPX   128        // threads in x; TPX*4 == IMG (full row per block-row)
#define TPY   2          // row-groups per block

struct Row5 { float4 x, y, xx, yy, xy; };

__device__ __forceinline__ float4 f4zero() { return make_float4(0.f, 0.f, 0.f, 0.f); }

__device__ __forceinline__ Row5 load_row(const float* __restrict__ gx,
                                         const float* __restrict__ gy,
                                         size_t base, int h, int tx, int lane)
{
    Row5 r;
    if ((unsigned)h >= (unsigned)IMG) {
        r.x = f4zero(); r.y = f4zero(); r.xx = f4zero(); r.yy = f4zero(); r.xy = f4zero();
        return r;
    }
    const size_t rowoff = base + (size_t)h * IMG;
    float4 a = *((const float4*)(gx + rowoff) + tx);
    float4 b = *((const float4*)(gy + rowoff) + tx);

    // horizontal neighbors: last elem of lane-1's vector, first elem of lane+1's
    float aL = __shfl_up_sync(0xffffffffu, a.w, 1);
    float bL = __shfl_up_sync(0xffffffffu, b.w, 1);
    float aR = __shfl_down_sync(0xffffffffu, a.x, 1);
    float bR = __shfl_down_sync(0xffffffffu, b.x, 1);

    // warp-boundary lanes fetch the neighbor scalar directly (zero at image edge)
    const int colL = tx * 4 - 1;
    const int colR = tx * 4 + 4;
    if (lane == 0) {
        bool ok = (colL >= 0);
        aL = ok ? gx[rowoff + colL] : 0.f;
        bL = ok ? gy[rowoff + colL] : 0.f;
    }
    if (lane == 31) {
        bool ok = (colR < IMG);
        aR = ok ? gx[rowoff + colR] : 0.f;
        bR = ok ? gy[rowoff + colR] : 0.f;
    }

    // horizontal 3-tap sums for the 4 output columns
    r.x = make_float4(aL + a.x + a.y,  a.x + a.y + a.z,  a.y + a.z + a.w,  a.z + a.w + aR);
    r.y = make_float4(bL + b.x + b.y,  b.x + b.y + b.z,  b.y + b.z + b.w,  b.z + b.w + bR);

    float pL = aL * aL, p0 = a.x * a.x, p1 = a.y * a.y, p2 = a.z * a.z, p3 = a.w * a.w, pR = aR * aR;
    r.xx = make_float4(pL + p0 + p1,  p0 + p1 + p2,  p1 + p2 + p3,  p2 + p3 + pR);

    float qL = bL * bL, q0 = b.x * b.x, q1 = b.y * b.y, q2 = b.z * b.z, q3 = b.w * b.w, qR = bR * bR;
    r.yy = make_float4(qL + q0 + q1,  q0 + q1 + q2,  q1 + q2 + q3,  q2 + q3 + qR);

    float mL = aL * bL, m0 = a.x * b.x, m1 = a.y * b.y, m2 = a.z * b.z, m3 = a.w * b.w, mR = aR * bR;
    r.xy = make_float4(mL + m0 + m1,  m0 + m1 + m2,  m1 + m2 + m3,  m2 + m3 + mR);

    return r;
}

__device__ __forceinline__ float ssim_px(float sx, float sy, float sxx, float syy,
                                         float sxy, float inv)
{
    const float C1 = 1e-4f;    // 0.01^2
    const float C2 = 9e-4f;    // 0.03^2
    float mux = sx * inv;
    float muy = sy * inv;
    float sigx  = fmaf(-mux, mux, sxx * inv);
    float sigy  = fmaf(-muy, muy, syy * inv);
    float sigxy = fmaf(-mux, muy, sxy * inv);
    float num = fmaf(2.f * mux, muy, C1) * fmaf(2.f, sigxy, C2);
    float den = fmaf(mux, mux, fmaf(muy, muy, C1)) * (sigx + sigy + C2) + 1e-12f;
    float s = __fdividef(num, den);
    return fminf(fmaxf((1.f - s) * 0.5f, 0.f), 1.f);
}

__global__ __launch_bounds__(TPX * TPY)
void ssim_kernel(const float* __restrict__ gx,
                 const float* __restrict__ gy,
                 float* __restrict__ gout)
{
    const int tx   = threadIdx.x;          // 0..127, owns columns [4tx, 4tx+4)
    const int lane = tx & 31;
    const int plane = blockIdx.z;
    const size_t base = (size_t)plane * (IMG * IMG);
    const int h0 = (blockIdx.y * TPY + threadIdx.y) * ROWS;

    // x-direction valid-tap counts for this thread's 4 columns
    float4 cx = make_float4(3.f, 3.f, 3.f, 3.f);
    if (tx == 0)       cx.x = 2.f;
    if (tx == TPX - 1) cx.w = 2.f;

    Row5 p = load_row(gx, gy, base, h0 - 1, tx, lane);
    Row5 c = load_row(gx, gy, base, h0,     tx, lane);

    float4* out4 = (float4*)(gout + base);

    #pragma unroll
    for (int r = 0; r < ROWS; r++) {
        const int h = h0 + r;
        Row5 n = load_row(gx, gy, base, h + 1, tx, lane);

        const float cy = 3.f - (float)(h == 0) - (float)(h == IMG - 1);
        float4 inv;
        inv.y = __fdividef(1.f, cy * 3.f);
        inv.z = inv.y;
        inv.x = (cx.x == 3.f) ? inv.y : __fdividef(1.f, cy * cx.x);
        inv.w = (cx.w == 3.f) ? inv.y : __fdividef(1.f, cy * cx.w);

        // vertical 3-tap sums
        float4 Sx  = make_float4(p.x.x + c.x.x + n.x.x,   p.x.y + c.x.y + n.x.y,
                                 p.x.z + c.x.z + n.x.z,   p.x.w + c.x.w + n.x.w);
        float4 Sy  = make_float4(p.y.x + c.y.x + n.y.x,   p.y.y + c.y.y + n.y.y,
                                 p.y.z + c.y.z + n.y.z,   p.y.w + c.y.w + n.y.w);
        float4 Sxx = make_float4(p.xx.x + c.xx.x + n.xx.x, p.xx.y + c.xx.y + n.xx.y,
                                 p.xx.z + c.xx.z + n.xx.z, p.xx.w + c.xx.w + n.xx.w);
        float4 Syy = make_float4(p.yy.x + c.yy.x + n.yy.x, p.yy.y + c.yy.y + n.yy.y,
                                 p.yy.z + c.yy.z + n.yy.z, p.yy.w + c.yy.w + n.yy.w);
        float4 Sxy = make_float4(p.xy.x + c.xy.x + n.xy.x, p.xy.y + c.xy.y + n.xy.y,
                                 p.xy.z + c.xy.z + n.xy.z, p.xy.w + c.xy.w + n.xy.w);

        float4 o;
        o.x = ssim_px(Sx.x, Sy.x, Sxx.x, Syy.x, Sxy.x, inv.x);
        o.y = ssim_px(Sx.y, Sy.y, Sxx.y, Syy.y, Sxy.y, inv.y);
        o.z = ssim_px(Sx.z, Sy.z, Sxx.z, Syy.z, Sxy.z, inv.z);
        o.w = ssim_px(Sx.w, Sy.w, Sxx.w, Syy.w, Sxy.w, inv.w);

        out4[(size_t)h * (IMG / 4) + tx] = o;

        p = c;
        c = n;
    }
}

extern "C" void kernel_launch(void* const* d_in, const int* in_sizes, int n_in,
                              void* d_out, int out_size)
{
    const float* x = (const float*)d_in[0];
    const float* y = (const float*)d_in[1];
    float* out = (float*)d_out;

    dim3 block(TPX, TPY, 1);                       // 256 threads
    dim3 grid(1, IMG / (TPY * ROWS), 16 * 3);      // 1 x 32 x 48 = 1536 blocks
    ssim_kernel<<<grid, block>>>(x, y, out);
}

// round 4
// speedup vs baseline: 1.4598x; 1.1525x over previous
#include <cuda_runtime.h>
#include <cuda_bf16.h>
#include <cstdint>

// SSIM loss map: out = clip((1 - SSIM_3x3(x,y)) * 0.5, 0, 1)
// NCHW fp32, 16x3x512x512 = 48 planes of 512x512.
// Register-sliding, shared-memory-free. Each thread owns a 2-wide column
// strip; the 2-column pair is processed with packed f32x2 math (Blackwell).

#define IMG   512
#define ROWS  8           // output rows per thread
#define TPX   256         // threads per block; TPX*2 == IMG (full row width)

typedef unsigned long long u64;

// ---- packed f32x2 helpers (sm_100+) ----
__device__ __forceinline__ u64 pk(float x, float y) {
    u64 r; asm("mov.b64 %0, {%1, %2};" : "=l"(r) : "f"(x), "f"(y)); return r;
}
__device__ __forceinline__ float2 unpk(u64 v) {
    float2 r; asm("mov.b64 {%0, %1}, %2;" : "=f"(r.x), "=f"(r.y) : "l"(v)); return r;
}
__device__ __forceinline__ u64 add2(u64 a, u64 b) {
    u64 r; asm("add.rn.f32x2 %0, %1, %2;" : "=l"(r) : "l"(a), "l"(b)); return r;
}
__device__ __forceinline__ u64 sub2(u64 a, u64 b) {
    u64 r; asm("sub.rn.f32x2 %0, %1, %2;" : "=l"(r) : "l"(a), "l"(b)); return r;
}
__device__ __forceinline__ u64 mul2(u64 a, u64 b) {
    u64 r; asm("mul.rn.f32x2 %0, %1, %2;" : "=l"(r) : "l"(a), "l"(b)); return r;
}
__device__ __forceinline__ u64 fma2(u64 a, u64 b, u64 c) {
    u64 r; asm("fma.rn.f32x2 %0, %1, %2, %3;" : "=l"(r) : "l"(a), "l"(b), "l"(c)); return r;
}

// per input row, horizontal 3-tap sums for this thread's 2 output columns,
// packed as f32x2 (lane .x = col 2tx, lane .y = col 2tx+1)
struct Stat { u64 x, y, xx, yy, xy; };

__device__ __forceinline__ Stat row_stats(const float* __restrict__ gx,
                                          const float* __restrict__ gy,
                                          size_t base, int h, int tx, int lane)
{
    Stat s;
    if ((unsigned)h >= (unsigned)IMG) {           // warp-uniform branch
        s.x = s.y = s.xx = s.yy = s.xy = 0ull;    // (0.f,0.f)
        return s;
    }
    const size_t rowoff = base + (size_t)h * IMG;
    float2 a = *((const float2*)(gx + rowoff) + tx);
    float2 b = *((const float2*)(gy + rowoff) + tx);

    // horizontal neighbors across lanes
    float aL = __shfl_up_sync(0xffffffffu, a.y, 1);
    float bL = __shfl_up_sync(0xffffffffu, b.y, 1);
    float aR = __shfl_down_sync(0xffffffffu, a.x, 1);
    float bR = __shfl_down_sync(0xffffffffu, b.x, 1);

    // warp-boundary lanes fetch neighbor scalar directly (zero at image edge)
    if (lane == 0) {
        const int colL = tx * 2 - 1;
        bool ok = (colL >= 0);
        aL = ok ? gx[rowoff + colL] : 0.f;
        bL = ok ? gy[rowoff + colL] : 0.f;
    }
    if (lane == 31) {
        const int colR = tx * 2 + 2;
        bool ok = (colR < IMG);
        aR = ok ? gx[rowoff + colR] : 0.f;
        bR = ok ? gy[rowoff + colR] : 0.f;
    }

    // shared-partial horizontal sums
    float sa = a.x + a.y;
    s.x = pk(aL + sa, sa + aR);
    float sb = b.x + b.y;
    s.y = pk(bL + sb, sb + bR);
    float pa = fmaf(a.x, a.x, a.y * a.y);
    s.xx = pk(fmaf(aL, aL, pa), fmaf(aR, aR, pa));
    float pb = fmaf(b.x, b.x, b.y * b.y);
    s.yy = pk(fmaf(bL, bL, pb), fmaf(bR, bR, pb));
    float pm = fmaf(a.x, b.x, a.y * b.y);
    s.xy = pk(fmaf(aL, bL, pm), fmaf(aR, bR, pm));
    return s;
}

__global__ __launch_bounds__(TPX)
void ssim_kernel(const float* __restrict__ gx,
                 const float* __restrict__ gy,
                 float* __restrict__ gout)
{
    const int tx   = threadIdx.x;              // 0..255, cols [2tx, 2tx+1]
    const int lane = tx & 31;
    const size_t base = (size_t)blockIdx.z * (IMG * IMG);
    const int h0 = blockIdx.y * ROWS;

    const float THIRD = 1.f / 3.f;
    // reciprocal x-direction tap counts for the 2 columns
    float2 rcx = make_float2(tx == 0 ? 0.5f : THIRD,
                             tx == TPX - 1 ? 0.5f : THIRD);

    const u64 TWO2 = pk(2.f, 2.f);
    const u64 C12  = pk(1e-4f, 1e-4f);
    const u64 C22  = pk(9e-4f, 9e-4f);
    const u64 EPS2 = pk(1e-12f, 1e-12f);

    Stat p = row_stats(gx, gy, base, h0 - 1, tx, lane);
    Stat c = row_stats(gx, gy, base, h0,     tx, lane);

    float2* out2 = (float2*)(gout + base);

    #pragma unroll
    for (int r = 0; r < ROWS; r++) {
        const int h = h0 + r;
        Stat n = row_stats(gx, gy, base, h + 1, tx, lane);

        const float rcy = (h == 0 || h == IMG - 1) ? 0.5f : THIRD;
        const u64 inv = pk(rcx.x * rcy, rcx.y * rcy);

        // vertical 3-tap sums (packed)
        u64 Sx  = add2(add2(p.x,  c.x),  n.x);
        u64 Sy  = add2(add2(p.y,  c.y),  n.y);
        u64 Sxx = add2(add2(p.xx, c.xx), n.xx);
        u64 Syy = add2(add2(p.yy, c.yy), n.yy);
        u64 Sxy = add2(add2(p.xy, c.xy), n.xy);

        // packed SSIM epilogue
        u64 mux = mul2(Sx, inv);
        u64 muy = mul2(Sy, inv);
        u64 mmx  = mul2(mux, mux);
        u64 mmy  = mul2(muy, muy);
        u64 mmxy = mul2(mux, muy);
        u64 sigx  = sub2(mul2(Sxx, inv), mmx);
        u64 sigy  = sub2(mul2(Syy, inv), mmy);
        u64 sigxy = sub2(mul2(Sxy, inv), mmxy);

        u64 t1  = fma2(mmxy, TWO2, C12);
        u64 t2  = fma2(sigxy, TWO2, C22);
        u64 num = mul2(t1, t2);
        u64 d1  = add2(add2(mmx, mmy), C12);
        u64 d2  = add2(add2(sigx, sigy), C22);
        u64 den = fma2(d1, d2, EPS2);

        float2 fn = unpk(num);
        float2 fd = unpk(den);
        float s0 = __fdividef(fn.x, fd.x);
        float s1 = __fdividef(fn.y, fd.y);
        float2 o;
        o.x = fminf(fmaxf(fmaf(s0, -0.5f, 0.5f), 0.f), 1.f);
        o.y = fminf(fmaxf(fmaf(s1, -0.5f, 0.5f), 0.f), 1.f);

        out2[(size_t)h * (IMG / 2) + tx] = o;

        p = c;
        c = n;
    }
}

extern "C" void kernel_launch(void* const* d_in, const int* in_sizes, int n_in,
                              void* d_out, int out_size)
{
    const float* x = (const float*)d_in[0];
    const float* y = (const float*)d_in[1];
    float* out = (float*)d_out;

    dim3 block(TPX, 1, 1);                    // 256 threads, one full row width
    dim3 grid(1, IMG / ROWS, 16 * 3);         // 1 x 64 x 48 = 3072 blocks
    ssim_kernel<<<grid, block>>>(x, y, out);
}

// round 5
// speedup vs baseline: 1.9724x; 1.3512x over previous
#include <cuda_runtime.h>
#include <cuda_bf16.h>
#include <cstdint>

// SSIM loss map: out = clip((1 - SSIM_3x3(x,y)) * 0.5, 0, 1)
// NCHW fp32, 16x3x512x512 = 48 planes of 512x512.
// Register-sliding, no shared memory. Each thread owns 2 columns (float2),
// packed f32x2 math for the column pair, and a one-iteration software
// pipeline: LDGs for row h+2 are issued at iteration r while the shuffles
// and stats consume the row loaded one iteration earlier.

#define IMG   512
#define ROWS  16          // output rows per thread
#define TPX   128         // threads per block; block covers TPX*2 = 256 cols

typedef unsigned long long u64;

// ---- packed f32x2 helpers (sm_100+) ----
__device__ __forceinline__ u64 pk(float x, float y) {
    u64 r; asm("mov.b64 %0, {%1, %2};" : "=l"(r) : "f"(x), "f"(y)); return r;
}
__device__ __forceinline__ float2 unpk(u64 v) {
    float2 r; asm("mov.b64 {%0, %1}, %2;" : "=f"(r.x), "=f"(r.y) : "l"(v)); return r;
}
__device__ __forceinline__ u64 add2(u64 a, u64 b) {
    u64 r; asm("add.rn.f32x2 %0, %1, %2;" : "=l"(r) : "l"(a), "l"(b)); return r;
}
__device__ __forceinline__ u64 sub2(u64 a, u64 b) {
    u64 r; asm("sub.rn.f32x2 %0, %1, %2;" : "=l"(r) : "l"(a), "l"(b)); return r;
}
__device__ __forceinline__ u64 mul2(u64 a, u64 b) {
    u64 r; asm("mul.rn.f32x2 %0, %1, %2;" : "=l"(r) : "l"(a), "l"(b)); return r;
}
__device__ __forceinline__ u64 fma2(u64 a, u64 b, u64 c) {
    u64 r; asm("fma.rn.f32x2 %0, %1, %2, %3;" : "=l"(r) : "l"(a), "l"(b), "l"(c)); return r;
}

// Raw row data: this thread's float2 from x and y, plus prefetched edge
// neighbor scalars (only meaningful in lanes 0 / 31).
struct Raw { float2 a, b; float eLa, eLb, eRa, eRb; };

// Horizontal 3-tap sums for the thread's 2 output columns, packed f32x2.
struct Stat { u64 x, y, xx, yy, xy; };

// Prefetch: LDGs only. No dependent consumption this iteration.
__device__ __forceinline__ Raw load_raw(const float* __restrict__ gxp,
                                        const float* __restrict__ gyp,
                                        int h, int c2, bool pl, bool pr)
{
    Raw r;
    r.a = make_float2(0.f, 0.f); r.b = make_float2(0.f, 0.f);
    r.eLa = r.eLb = r.eRa = r.eRb = 0.f;
    if ((unsigned)h < (unsigned)IMG) {             // warp-uniform branch
        const size_t ro = (size_t)h * IMG;
        r.a = *((const float2*)(gxp + ro) + c2);
        r.b = *((const float2*)(gyp + ro) + c2);
        if (pl) {                                   // lane 0: left neighbor
            const int colL = c2 * 2 - 1;
            if (colL >= 0) { r.eLa = gxp[ro + colL]; r.eLb = gyp[ro + colL]; }
        }
        if (pr) {                                   // lane 31: right neighbor
            const int colR = c2 * 2 + 2;
            if (colR < IMG) { r.eRa = gxp[ro + colR]; r.eRb = gyp[ro + colR]; }
        }
    }
    return r;
}

// Consume: shuffles (on registers loaded >= 1 iteration ago) + h-stats.
__device__ __forceinline__ Stat make_stats(const Raw& w, bool pl, bool pr)
{
    float aL = __shfl_up_sync(0xffffffffu, w.a.y, 1);
    float bL = __shfl_up_sync(0xffffffffu, w.b.y, 1);
    float aR = __shfl_down_sync(0xffffffffu, w.a.x, 1);
    float bR = __shfl_down_sync(0xffffffffu, w.b.x, 1);
    if (pl) { aL = w.eLa; bL = w.eLb; }
    if (pr) { aR = w.eRa; bR = w.eRb; }

    Stat s;
    float sa = w.a.x + w.a.y;
    s.x = pk(aL + sa, sa + aR);
    float sb = w.b.x + w.b.y;
    s.y = pk(bL + sb, sb + bR);
    float pa = fmaf(w.a.x, w.a.x, w.a.y * w.a.y);
    s.xx = pk(fmaf(aL, aL, pa), fmaf(aR, aR, pa));
    float pb = fmaf(w.b.x, w.b.x, w.b.y * w.b.y);
    s.yy = pk(fmaf(bL, bL, pb), fmaf(bR, bR, pb));
    float pm = fmaf(w.a.x, w.b.x, w.a.y * w.b.y);
    s.xy = pk(fmaf(aL, bL, pm), fmaf(aR, bR, pm));
    return s;
}

__global__ __launch_bounds__(TPX)
void ssim_kernel(const float* __restrict__ gx,
                 const float* __restrict__ gy,
                 float* __restrict__ gout)
{
    const int tx   = threadIdx.x;
    const int lane = tx & 31;
    const bool pl = (lane == 0);
    const bool pr = (lane == 31);
    const int c2 = blockIdx.x * TPX + tx;       // float2 index, 0..255
    const size_t base = (size_t)blockIdx.z * (IMG * IMG);
    const float* gxp = gx + base;
    const float* gyp = gy + base;
    const int h0 = blockIdx.y * ROWS;

    const float THIRD = 1.f / 3.f;
    float2 rcx = make_float2(c2 == 0 ? 0.5f : THIRD,
                             c2 == (IMG / 2 - 1) ? 0.5f : THIRD);

    const u64 TWO2 = pk(2.f, 2.f);
    const u64 C12  = pk(1e-4f, 1e-4f);
    const u64 C22  = pk(9e-4f, 9e-4f);
    const u64 EPS2 = pk(1e-12f, 1e-12f);

    // Pipeline fill: rows h0-1, h0 consumed immediately; h0+1 staged in rn.
    Stat p = make_stats(load_raw(gxp, gyp, h0 - 1, c2, pl, pr), pl, pr);
    Stat c = make_stats(load_raw(gxp, gyp, h0,     c2, pl, pr), pl, pr);
    Raw  rn = load_raw(gxp, gyp, h0 + 1, c2, pl, pr);

    float2* out2 = (float2*)(gout + base);

    #pragma unroll
    for (int r = 0; r < ROWS; r++) {
        const int h = h0 + r;

        // prefetch row h+2 (LDGs only; consumed next iteration)
        Raw rf = load_raw(gxp, gyp, h + 2, c2, pl, pr);

        // consume the row prefetched last iteration
        Stat n = make_stats(rn, pl, pr);

        const float rcy = (h == 0 || h == IMG - 1) ? 0.5f : THIRD;
        const u64 inv = pk(rcx.x * rcy, rcx.y * rcy);

        // vertical 3-tap sums (packed)
        u64 Sx  = add2(add2(p.x,  c.x),  n.x);
        u64 Sy  = add2(add2(p.y,  c.y),  n.y);
        u64 Sxx = add2(add2(p.xx, c.xx), n.xx);
        u64 Syy = add2(add2(p.yy, c.yy), n.yy);
        u64 Sxy = add2(add2(p.xy, c.xy), n.xy);

        // packed SSIM epilogue
        u64 mux = mul2(Sx, inv);
        u64 muy = mul2(Sy, inv);
        u64 mmx  = mul2(mux, mux);
        u64 mmy  = mul2(muy, muy);
        u64 mmxy = mul2(mux, muy);
        u64 sigx  = sub2(mul2(Sxx, inv), mmx);
        u64 sigy  = sub2(mul2(Syy, inv), mmy);
        u64 sigxy = sub2(mul2(Sxy, inv), mmxy);

        u64 t1  = fma2(mmxy, TWO2, C12);
        u64 t2  = fma2(sigxy, TWO2, C22);
        u64 num = mul2(t1, t2);
        u64 d1  = add2(add2(mmx, mmy), C12);
        u64 d2  = add2(add2(sigx, sigy), C22);
        u64 den = fma2(d1, d2, EPS2);

        float2 fn = unpk(num);
        float2 fd = unpk(den);
        float s0 = __fdividef(fn.x, fd.x);
        float s1 = __fdividef(fn.y, fd.y);
        float2 o;
        o.x = fminf(fmaxf(fmaf(s0, -0.5f, 0.5f), 0.f), 1.f);
        o.y = fminf(fmaxf(fmaf(s1, -0.5f, 0.5f), 0.f), 1.f);

        out2[(size_t)h * (IMG / 2) + c2] = o;

        p = c;
        c = n;
        rn = rf;
    }
}

extern "C" void kernel_launch(void* const* d_in, const int* in_sizes, int n_in,
                              void* d_out, int out_size)
{
    const float* x = (const float*)d_in[0];
    const float* y = (const float*)d_in[1];
    float* out = (float*)d_out;

    dim3 block(TPX, 1, 1);                            // 128 threads
    dim3 grid(IMG / (2 * TPX), IMG / ROWS, 16 * 3);   // 2 x 32 x 48 = 3072
    ssim_kernel<<<grid, block>>>(x, y, out);
}